// round 3
// baseline (speedup 1.0000x reference)
#include <cuda_runtime.h>

#define BB 64
#define HH 14
#define WWD 14
#define HW 196
#define CC 32
#define OO 10
#define NCH 14              // hw-chunks per batch
#define HWB (HW/NCH)        // 14 hw positions per block
#define CHALF 16            // c's per block
#define NCHUNK (NCH*2)      // 28 partial groups per batch (hw-chunk x c-half)
#define TPB 320             // 10 warps: warp = o, lane = colpair*16 + clow
#define EPSF 1e-9f
#define LOG2PI 1.8378770664093453f

// Scratch (fully rewritten every pass -> deterministic, graph-safe)
__device__ float g_partials[BB*NCHUNK*OO*33]; // [b][chunk][o][S0,S1[16],S2[16]]
__device__ float g_params[BB*OO*33];          // [b][o][K, ivar[16], muinv[16]]
__device__ int   g_count[BB];                 // arrival counters (winner resets to 0)

// ---------------------------------------------------------------------------
// Fused accumulate + (last block per batch) reduce.
// grid = (NCHUNK, BB), block = 320.
// ---------------------------------------------------------------------------
template<int PASS, int FINAL>
__global__ void __launch_bounds__(TPB, 2)
caps_fused(const float* __restrict__ pose,
           const float* __restrict__ act,
           const float* __restrict__ w,
           const float* __restrict__ beta_a,
           const float* __restrict__ beta_u,
           float inv_temp,
           float* __restrict__ out)
{
    __shared__ float sp[HWB][CHALF][17];  // pose tile (16 c's), padded
    __shared__ float sa[HWB][CHALF];
    __shared__ float ss[CHALF][11];       // softmax logits
    __shared__ float se[CHALF][11];       // softmax exps
    __shared__ int   s_win;

    const int b     = blockIdx.y;
    const int ch2   = blockIdx.x;
    const int ch    = ch2 >> 1;           // hw chunk
    const int chalf = ch2 & 1;            // c half
    const int hw0   = ch * HWB;
    const int c0    = chalf * CHALF;
    const int tid   = threadIdx.x;
    const int o     = tid >> 5;           // warp id
    const int lane  = tid & 31;
    const int cp    = lane >> 4;          // column pair: cols {2cp, 2cp+1}
    const int cl    = lane & 15;          // local c

    // ---- cooperative tile load (16 c's x 16 floats contiguous per hw) ----
    {
        const float* src = pose + ((size_t)(b * HW + hw0) * CC + c0) * 16;
        for (int idx = tid; idx < HWB * CHALF * 16; idx += TPB) {
            int hw_l = idx >> 8;              // /256
            int rem  = idx & 255;
            int c_l  = rem >> 4;
            int j    = rem & 15;
            sp[hw_l][c_l][j] = src[(size_t)hw_l * CC * 16 + rem];
        }
        const float* asrc = act + (size_t)(b * HW + hw0) * CC + c0;
        for (int idx = tid; idx < HWB * CHALF; idx += TPB) {
            sa[idx >> 4][idx & 15] = asrc[(idx >> 4) * CC + (idx & 15)];
        }
    }

    // ---- per-thread constants: 2 columns of w[c][o] -----------------------
    // local m=0..7  ->  d = (m>>1)*4 + 2*cp + (m&1)
    float wr[8];                               // wr[i*2+k] = w[i*4 + 2cp+k]
    {
        const float* wp = w + (size_t)((c0 + cl) * OO + o) * 16;
        #pragma unroll
        for (int i = 0; i < 4; i++) {
            wr[i*2+0] = wp[i*4 + 2*cp + 0];
            wr[i*2+1] = wp[i*4 + 2*cp + 1];
        }
    }

    float K = 0.f, iv[8], mi[8];
    if (PASS == 1) {
        const float* pp = g_params + (size_t)(b * OO + o) * 33;
        K = pp[0];
        #pragma unroll
        for (int m = 0; m < 8; m++) {
            const int d = (m >> 1) * 4 + 2*cp + (m & 1);
            iv[m] = pp[1 + d];
            mi[m] = pp[17 + d];
        }
    }

    float S0 = 0.f, S1[8], S2[8];
    #pragma unroll
    for (int m = 0; m < 8; m++) { S1[m] = 0.f; S2[m] = 0.f; }

    __syncthreads();

    // ---- main loop over hw positions --------------------------------------
    for (int t = 0; t < HWB; t++) {
        const int hw   = hw0 + t;
        const int h    = hw / WWD;
        const int wpos = hw % WWD;

        const float a = sa[t][cl];

        // votes for my 2 columns: v[i*2+k] = sum_j p[i*4+j] * w[j*4+2cp+k]
        float v[8];
        #pragma unroll
        for (int i = 0; i < 4; i++) {
            const float p0 = sp[t][cl][i*4+0];
            const float p1 = sp[t][cl][i*4+1];
            const float p2 = sp[t][cl][i*4+2];
            const float p3 = sp[t][cl][i*4+3];
            // w rows j: wr holds column values; recompute per j from sp of row j?
            // NOTE: v[d]=sum_j p[i*4+j]*w[j*4+col] -> need w rows 0..3 of my cols:
            // wr[j*2+k] = w[j*4+2cp+k]
            v[i*2+0] = fmaf(p0, wr[0*2+0], fmaf(p1, wr[1*2+0],
                       fmaf(p2, wr[2*2+0], p3 * wr[3*2+0])));
            v[i*2+1] = fmaf(p0, wr[0*2+1], fmaf(p1, wr[1*2+1],
                       fmaf(p2, wr[2*2+1], p3 * wr[3*2+1])));
        }
        // coord addition: d=3 (i=0,col=3), d=7 (i=1,col=3) -> cp==1, k==1
        if (cp == 1) {
            v[0*2+1] += (wpos + 0.5f) * (1.0f / WWD);   // d=3
            v[1*2+1] += (h    + 0.5f) * (1.0f / HH);    // d=7
        }

        float ap;
        if (PASS == 0) {
            ap = a * 0.1f;
        } else {
            float e1 = 0.f, e2 = 0.f;
            #pragma unroll
            for (int m = 0; m < 8; m++) {
                const float vd = v[m];
                e1 = fmaf(vd * vd, iv[m], e1);
                e2 = fmaf(vd,      mi[m], e2);
            }
            // partner (other column pair, same c, same warp) has the rest
            e1 += __shfl_xor_sync(0xFFFFFFFFu, e1, 16);
            e2 += __shfl_xor_sync(0xFFFFFFFFu, e2, 16);
            const float s = K + e2 - 0.5f * e1;
            if (cp == 0) ss[cl][o] = s;
            __syncthreads();
            float mx = ss[cl][0];
            #pragma unroll
            for (int oo = 1; oo < OO; oo++) mx = fmaxf(mx, ss[cl][oo]);
            const float e = __expf(s - mx);
            if (cp == 0) se[cl][o] = e;
            __syncthreads();
            float den = se[cl][0];
            #pragma unroll
            for (int oo = 1; oo < OO; oo++) den += se[cl][oo];
            ap = a * __fdividef(e, den);
        }

        S0 += ap;
        #pragma unroll
        for (int m = 0; m < 8; m++) {
            const float t1 = ap * v[m];
            S1[m] += t1;
            S2[m]  = fmaf(t1, v[m], S2[m]);
        }
    }

    // ---- reduce over 16 c's (in-halfwarp shuffles) ------------------------
    #pragma unroll
    for (int off = 8; off > 0; off >>= 1) {
        S0 += __shfl_xor_sync(0xFFFFFFFFu, S0, off);
        #pragma unroll
        for (int m = 0; m < 8; m++) {
            S1[m] += __shfl_xor_sync(0xFFFFFFFFu, S1[m], off);
            S2[m] += __shfl_xor_sync(0xFFFFFFFFu, S2[m], off);
        }
    }
    if (cl == 0) {
        float* dst = g_partials + (size_t)((b * NCHUNK + ch2) * OO + o) * 33;
        if (cp == 0) dst[0] = S0;
        #pragma unroll
        for (int m = 0; m < 8; m++) {
            const int d = (m >> 1) * 4 + 2*cp + (m & 1);
            dst[1 + d]  = S1[m];
            dst[17 + d] = S2[m];
        }
    }

    // ---- last block per batch performs the reduce -------------------------
    __syncthreads();
    if (tid == 0) {
        __threadfence();
        int prev = atomicAdd(&g_count[b], 1);
        s_win = (prev == NCHUNK - 1);
    }
    __syncthreads();
    if (!s_win) return;
    __threadfence();

    if (tid < OO * 16) {
        const int ro = tid >> 4;
        const int rd = tid & 15;

        float R0 = 0.f, R1 = 0.f, R2 = 0.f;
        #pragma unroll 4
        for (int g = 0; g < NCHUNK; g++) {
            const float* p = g_partials + (size_t)((b * NCHUNK + g) * OO + ro) * 33;
            R0 += p[0];
            R1 += p[1 + rd];
            R2 += p[17 + rd];
        }

        const float rs     = R0 + EPSF;
        const float inv_rs = 1.0f / rs;
        const float mu     = R1 * inv_rs;
        const float var    = fmaxf(R2 * inv_rs - mu * mu, 0.0f) + EPSF;
        const float lv     = __logf(var);
        const float ivar   = 1.0f / var;
        const float muinv  = mu * ivar;
        const float mive   = mu * muinv;

        float sumlv = lv, summive = mive;
        #pragma unroll
        for (int off = 1; off < 16; off <<= 1) {
            sumlv   += __shfl_xor_sync(0xFFFFFFFFu, sumlv,   off);
            summive += __shfl_xor_sync(0xFFFFFFFFu, summive, off);
        }

        const float cost = rs * (16.0f * beta_u[ro] + 0.5f * sumlv);
        const float x    = inv_temp * (beta_a[ro] - cost);
        const float actv = 1.0f / (1.0f + __expf(-x));

        if (FINAL) {
            out[(size_t)(b * OO + ro) * 16 + rd] = mu;
            if (rd == 0) out[BB * OO * 16 + b * OO + ro] = actv;
        } else {
            float* pp = g_params + (size_t)(b * OO + ro) * 33;
            pp[1 + rd]  = ivar;
            pp[17 + rd] = muinv;
            if (rd == 0)
                pp[0] = __logf(actv + EPSF)
                      - 0.5f * (16.0f * LOG2PI + sumlv)
                      - 0.5f * summive;
        }
    }
    if (tid == 0) g_count[b] = 0;   // restore for next launch / graph replay
}

// ---------------------------------------------------------------------------
extern "C" void kernel_launch(void* const* d_in, const int* in_sizes, int n_in,
                              void* d_out, int out_size)
{
    const float* pose = (const float*)d_in[0];
    const float* act  = (const float*)d_in[1];
    const float* w    = (const float*)d_in[2];
    const float* ba   = (const float*)d_in[3];
    const float* bu   = (const float*)d_in[4];
    float* out = (float*)d_out;

    dim3 ga(NCHUNK, BB);

    caps_fused<0,0><<<ga, TPB>>>(pose, act, w, ba, bu, 1.0f, out);
    caps_fused<1,0><<<ga, TPB>>>(pose, act, w, ba, bu, 2.0f, out);
    caps_fused<1,1><<<ga, TPB>>>(pose, act, w, ba, bu, 3.0f, out);
}

// round 4
// speedup vs baseline: 1.5644x; 1.5644x over previous
#include <cuda_runtime.h>

#define BB 64
#define HH 14
#define WWD 14
#define HW 196
#define CC 32
#define OO 10
#define NCH 14              // hw-chunks per batch
#define HWB (HW/NCH)        // 14 hw positions per block
#define TPB 320             // 10 warps: warp = o, lane = c
#define EPSF 1e-9f
#define LOG2PI 1.8378770664093453f

typedef unsigned long long u64;

// ---- f32x2 packed math (Blackwell) ---------------------------------------
__device__ __forceinline__ u64 pack2(float lo, float hi) {
    u64 r; asm("mov.b64 %0, {%1,%2};" : "=l"(r) : "f"(lo), "f"(hi)); return r;
}
__device__ __forceinline__ u64 pdup(float x) { return pack2(x, x); }
__device__ __forceinline__ void unpack2(u64 v, float& lo, float& hi) {
    asm("mov.b64 {%0,%1}, %2;" : "=f"(lo), "=f"(hi) : "l"(v));
}
__device__ __forceinline__ u64 fma2(u64 a, u64 b, u64 c) {
    u64 d; asm("fma.rn.f32x2 %0,%1,%2,%3;" : "=l"(d) : "l"(a), "l"(b), "l"(c)); return d;
}
__device__ __forceinline__ u64 mul2(u64 a, u64 b) {
    u64 d; asm("mul.rn.f32x2 %0,%1,%2;" : "=l"(d) : "l"(a), "l"(b)); return d;
}
__device__ __forceinline__ u64 add2(u64 a, u64 b) {
    u64 d; asm("add.rn.f32x2 %0,%1,%2;" : "=l"(d) : "l"(a), "l"(b)); return d;
}

// Scratch (fully rewritten every pass -> deterministic, graph-safe)
__device__ float g_partials[BB*NCH*OO*33]; // [b][chunk][o][S0,S1[16],S2[16]]
__device__ float g_params[BB*OO*33];       // [b][o][K, ivar[16], muinv[16]]
__device__ int   g_count[BB];              // arrival counters (winner resets)

// ---------------------------------------------------------------------------
// Fused accumulate + (last block per batch) reduce. grid=(NCH,BB), block=320.
// ---------------------------------------------------------------------------
template<int PASS, int FINAL>
__global__ void __launch_bounds__(TPB, 2)
caps_fused(const float* __restrict__ pose,
           const float* __restrict__ act,
           const float* __restrict__ w,
           const float* __restrict__ beta_a,
           const float* __restrict__ beta_u,
           float inv_temp,
           float* __restrict__ out)
{
    __shared__ float4 sp4[HWB][CC][5];   // pose rows as float4, 80B stride (conflict-free)
    __shared__ float  sa[HWB][CC];
    __shared__ float  ss[CC][11];        // softmax logits
    __shared__ float  se[CC][11];        // softmax exps
    __shared__ float4 prm[OO][8];        // (iv[2k],iv[2k+1],mi[2k],mi[2k+1])
    __shared__ float  Ksm[OO];
    __shared__ int    s_win;

    const int b    = blockIdx.y;
    const int ch   = blockIdx.x;
    const int hw0  = ch * HWB;
    const int tid  = threadIdx.x;
    const int o    = tid >> 5;           // warp id
    const int c    = tid & 31;           // lane id

    // ---- cooperative tile load -------------------------------------------
    {
        const float4* src4 = (const float4*)(pose + (size_t)(b * HW + hw0) * CC * 16);
        for (int idx = tid; idx < HWB * CC * 4; idx += TPB) {
            int t_l = idx >> 7;             // /(CC*4)
            int rem = idx & 127;
            sp4[t_l][rem >> 2][rem & 3] = src4[idx];
        }
        const float* asrc = act + (size_t)(b * HW + hw0) * CC;
        for (int idx = tid; idx < HWB * CC; idx += TPB)
            sa[idx >> 5][idx & 31] = asrc[idx];

        if (PASS == 1) {
            if (tid < OO * 8) {
                const int po = tid >> 3, pk = tid & 7;
                const float* pp = g_params + (size_t)(b * OO + po) * 33;
                prm[po][pk] = make_float4(pp[1 + 2*pk], pp[2 + 2*pk],
                                          pp[17 + 2*pk], pp[18 + 2*pk]);
            }
            if (tid < OO) Ksm[tid] = g_params[(size_t)(b * OO + tid) * 33];
        }
    }

    // ---- per-thread constants: w[c][o] rows packed as f32x2 pairs --------
    u64 wv[4][2];
    {
        const float4* wp = (const float4*)(w + (size_t)(c * OO + o) * 16);
        #pragma unroll
        for (int j = 0; j < 4; j++) {
            float4 r = wp[j];
            wv[j][0] = pack2(r.x, r.y);   // cols 0,1
            wv[j][1] = pack2(r.z, r.w);   // cols 2,3
        }
    }

    float S0 = 0.f;
    u64 S1[8], S2[8];
    #pragma unroll
    for (int k = 0; k < 8; k++) { S1[k] = 0ull; S2[k] = 0ull; }

    __syncthreads();

    const float K = (PASS == 1) ? Ksm[o] : 0.f;

    // ---- main loop over hw positions -------------------------------------
    for (int t = 0; t < HWB; t++) {
        const int hw   = hw0 + t;
        const int h    = hw / WWD;
        const int wpos = hw - h * WWD;

        const float a = sa[t][c];

        // votes: v[k] packs d=2k,2k+1.  v[i*2+cp] = sum_j P_i[j] * wv[j][cp]
        u64 v[8];
        #pragma unroll
        for (int i = 0; i < 4; i++) {
            const float4 P = sp4[t][c][i];
            const u64 p0 = pdup(P.x), p1 = pdup(P.y), p2 = pdup(P.z), p3 = pdup(P.w);
            v[i*2+0] = fma2(p0, wv[0][0], fma2(p1, wv[1][0],
                       fma2(p2, wv[2][0], mul2(p3, wv[3][0]))));
            v[i*2+1] = fma2(p0, wv[0][1], fma2(p1, wv[1][1],
                       fma2(p2, wv[2][1], mul2(p3, wv[3][1]))));
        }
        // coord addition: d=3 (k=1 hi), d=7 (k=3 hi)
        v[1] = add2(v[1], pack2(0.f, (wpos + 0.5f) * (1.0f / WWD)));
        v[3] = add2(v[3], pack2(0.f, (h    + 0.5f) * (1.0f / HH)));

        float ap;
        if (PASS == 0) {
            ap = a * 0.1f;
        } else {
            u64 e1 = 0ull, e2 = 0ull;
            #pragma unroll
            for (int k = 0; k < 8; k++) {
                const longlong2 q = *(const longlong2*)&prm[o][k];  // uniform LDS.128
                const u64 iv2 = (u64)q.x, mi2 = (u64)q.y;
                const u64 vk  = v[k];
                e1 = fma2(mul2(vk, vk), iv2, e1);
                e2 = fma2(vk, mi2, e2);
            }
            float e1l, e1h, e2l, e2h;
            unpack2(e1, e1l, e1h);
            unpack2(e2, e2l, e2h);
            const float s = fmaf(-0.5f, e1l + e1h, K + e2l + e2h);
            ss[c][o] = s;
            __syncthreads();
            float mx = ss[c][0];
            #pragma unroll
            for (int oo = 1; oo < OO; oo++) mx = fmaxf(mx, ss[c][oo]);
            const float e = __expf(s - mx);
            se[c][o] = e;
            __syncthreads();
            float den = se[c][0];
            #pragma unroll
            for (int oo = 1; oo < OO; oo++) den += se[c][oo];
            ap = a * __fdividef(e, den);
        }

        S0 += ap;
        const u64 ap2 = pdup(ap);
        #pragma unroll
        for (int k = 0; k < 8; k++) {
            const u64 t1 = mul2(ap2, v[k]);
            S1[k] = add2(S1[k], t1);
            S2[k] = fma2(t1, v[k], S2[k]);
        }
    }

    // ---- reduce over 32 c's (warp shuffles on packed u64) ----------------
    #pragma unroll
    for (int off = 16; off > 0; off >>= 1) {
        S0 += __shfl_xor_sync(0xFFFFFFFFu, S0, off);
        #pragma unroll
        for (int k = 0; k < 8; k++) {
            S1[k] += 0;  // keep live
            u64 a1 = __shfl_xor_sync(0xFFFFFFFFu, S1[k], off);
            u64 a2 = __shfl_xor_sync(0xFFFFFFFFu, S2[k], off);
            S1[k] = add2(S1[k], a1);
            S2[k] = add2(S2[k], a2);
        }
    }
    if (c == 0) {
        float* dst = g_partials + (size_t)((b * NCH + ch) * OO + o) * 33;
        dst[0] = S0;
        #pragma unroll
        for (int k = 0; k < 8; k++) {
            float lo, hi;
            unpack2(S1[k], lo, hi);
            dst[1 + 2*k] = lo;  dst[2 + 2*k] = hi;
            unpack2(S2[k], lo, hi);
            dst[17 + 2*k] = lo; dst[18 + 2*k] = hi;
        }
    }

    // ---- last block per batch performs the reduce ------------------------
    __syncthreads();
    if (tid == 0) {
        __threadfence();
        int prev = atomicAdd(&g_count[b], 1);
        s_win = (prev == NCH - 1);
    }
    __syncthreads();
    if (!s_win) return;
    __threadfence();

    if (tid < OO * 16) {
        const int ro = tid >> 4;
        const int rd = tid & 15;

        float R0 = 0.f, R1 = 0.f, R2 = 0.f;
        #pragma unroll 2
        for (int g = 0; g < NCH; g++) {
            const float* p = g_partials + (size_t)((b * NCH + g) * OO + ro) * 33;
            R0 += p[0];
            R1 += p[1 + rd];
            R2 += p[17 + rd];
        }

        const float rs     = R0 + EPSF;
        const float inv_rs = 1.0f / rs;
        const float mu     = R1 * inv_rs;
        const float var    = fmaxf(R2 * inv_rs - mu * mu, 0.0f) + EPSF;
        const float lv     = __logf(var);
        const float ivar   = 1.0f / var;
        const float muinv  = mu * ivar;
        const float mive   = mu * muinv;

        float sumlv = lv, summive = mive;
        #pragma unroll
        for (int off = 1; off < 16; off <<= 1) {
            sumlv   += __shfl_xor_sync(0xFFFFFFFFu, sumlv,   off);
            summive += __shfl_xor_sync(0xFFFFFFFFu, summive, off);
        }

        const float cost = rs * (16.0f * beta_u[ro] + 0.5f * sumlv);
        const float x    = inv_temp * (beta_a[ro] - cost);
        const float actv = 1.0f / (1.0f + __expf(-x));

        if (FINAL) {
            out[(size_t)(b * OO + ro) * 16 + rd] = mu;
            if (rd == 0) out[BB * OO * 16 + b * OO + ro] = actv;
        } else {
            float* pp = g_params + (size_t)(b * OO + ro) * 33;
            pp[1 + rd]  = ivar;
            pp[17 + rd] = muinv;
            if (rd == 0)
                pp[0] = __logf(actv + EPSF)
                      - 0.5f * (16.0f * LOG2PI + sumlv)
                      - 0.5f * summive;
        }
    }
    if (tid == 0) g_count[b] = 0;   // restore for next launch / graph replay
}

// ---------------------------------------------------------------------------
extern "C" void kernel_launch(void* const* d_in, const int* in_sizes, int n_in,
                              void* d_out, int out_size)
{
    const float* pose = (const float*)d_in[0];
    const float* act  = (const float*)d_in[1];
    const float* w    = (const float*)d_in[2];
    const float* ba   = (const float*)d_in[3];
    const float* bu   = (const float*)d_in[4];
    float* out = (float*)d_out;

    dim3 ga(NCH, BB);

    caps_fused<0,0><<<ga, TPB>>>(pose, act, w, ba, bu, 1.0f, out);
    caps_fused<1,0><<<ga, TPB>>>(pose, act, w, ba, bu, 2.0f, out);
    caps_fused<1,1><<<ga, TPB>>>(pose, act, w, ba, bu, 3.0f, out);
}